// round 14
// baseline (speedup 1.0000x reference)
#include <cuda_runtime.h>
#include <cuda_fp16.h>
#include <math.h>
#include <stdint.h>

#define T_TOK   4096
#define C_DIM   1024
#define FF_DIM  4096
#define E_NUM   8
#define PROWS   9216            // 8192 rows + per-expert pad to 128
#define MTILES  (PROWS/128)     // 72

#define KCH     64              // K columns per pipeline chunk
#define LDSE    72              // padded fp16 elems per 64-elem row (144B stride)
#define NTILE   256
#define TILE_A  (128*LDSE*2)    // 18432 bytes
#define TILE_BB (NTILE*LDSE*2)  // 36864 bytes
#define STAGE_B (TILE_A+TILE_BB) // 55296
#define NSTAGE  3
#define SMEM_TOTAL (NSTAGE*STAGE_B)   // 165888, 1 CTA/SM, 8 warps

#define HSTG2   144             // H staging stride (128B data + 16B pad), 16B-aligned
#define YSTG2   272             // Y staging stride (256B data + 16B pad), 16B-aligned

// ---------------- scratch (static device globals; no allocation) ----------------
__device__ int   g_counts[E_NUM];
__device__ int   g_aoff[E_NUM];
__device__ int   g_cursor[E_NUM];
__device__ int   g_tile_e[MTILES];
__device__ int   g_top_idx[T_TOK * 2];
__device__ float g_top_w[T_TOK * 2];
__device__ int   g_rowtok[PROWS];
__device__ float g_rowgate[PROWS];
__device__ int   g_tokrow[T_TOK * 2];

__device__ __align__(128) __half g_a[(size_t)PROWS * C_DIM];
__device__ __align__(128) __half g_w1[(size_t)E_NUM * FF_DIM * C_DIM];
__device__ __align__(128) __half g_w2[(size_t)E_NUM * C_DIM * FF_DIM];
__device__ __align__(128) __half g_h[(size_t)PROWS * FF_DIM];
__device__ __align__(128) float  g_y[(size_t)PROWS * C_DIM];

// ---------------- PTX helpers (baseline-PTX only) ----------------
__device__ __forceinline__ uint32_t s2u(const void* p) {
    uint32_t a;
    asm("{ .reg .u64 t; cvta.to.shared.u64 t, %1; cvt.u32.u64 %0, t; }" : "=r"(a) : "l"(p));
    return a;
}
__device__ __forceinline__ void cpasync16(uint32_t dst, const void* src) {
    asm volatile("cp.async.cg.shared.global [%0], [%1], 16;" :: "r"(dst), "l"(src));
}
__device__ __forceinline__ void cp_commit() {
    asm volatile("cp.async.commit_group;" ::: "memory");
}
__device__ __forceinline__ void ldmx4(uint32_t* r, uint32_t addr) {
    asm volatile("ldmatrix.sync.aligned.m8n8.x4.shared.b16 {%0,%1,%2,%3}, [%4];"
                 : "=r"(r[0]), "=r"(r[1]), "=r"(r[2]), "=r"(r[3]) : "r"(addr));
}
__device__ __forceinline__ void mma16816(float* c, const uint32_t* a, const uint32_t* b) {
    asm volatile("mma.sync.aligned.m16n8k16.row.col.f32.f16.f16.f32 "
                 "{%0,%1,%2,%3}, {%4,%5,%6,%7}, {%8,%9}, {%0,%1,%2,%3};"
                 : "+f"(c[0]), "+f"(c[1]), "+f"(c[2]), "+f"(c[3])
                 : "r"(a[0]), "r"(a[1]), "r"(a[2]), "r"(a[3]), "r"(b[0]), "r"(b[1]));
}

// ---------------- routing ----------------
__global__ void init_kernel() {
    int i = blockIdx.x * blockDim.x + threadIdx.x;
    if (i < E_NUM) g_counts[i] = 0;
    if (i < PROWS) g_rowtok[i] = -1;
}

__global__ void router_kernel(const float* __restrict__ x, const float* __restrict__ rw) {
    int gtid = blockIdx.x * blockDim.x + threadIdx.x;
    int t = gtid >> 5, lane = threadIdx.x & 31;
    if (t >= T_TOK) return;
    const float4* xr4 = (const float4*)(x + (size_t)t * C_DIM);
    const float4* rw4 = (const float4*)rw;
    float acc[E_NUM];
#pragma unroll
    for (int e = 0; e < E_NUM; e++) acc[e] = 0.f;
    for (int c4 = lane; c4 < C_DIM / 4; c4 += 32) {
        float4 xv = xr4[c4];
#pragma unroll
        for (int e = 0; e < E_NUM; e++) {
            float4 wv = rw4[e * (C_DIM / 4) + c4];
            acc[e] += xv.x * wv.x + xv.y * wv.y + xv.z * wv.z + xv.w * wv.w;
        }
    }
#pragma unroll
    for (int e = 0; e < E_NUM; e++)
#pragma unroll
        for (int o = 16; o; o >>= 1) acc[e] += __shfl_xor_sync(0xFFFFFFFFu, acc[e], o);
    if (lane == 0) {
        float m = acc[0];
#pragma unroll
        for (int e = 1; e < E_NUM; e++) m = fmaxf(m, acc[e]);
        float p[E_NUM], Z = 0.f;
#pragma unroll
        for (int e = 0; e < E_NUM; e++) { p[e] = expf(acc[e] - m); Z += p[e]; }
#pragma unroll
        for (int e = 0; e < E_NUM; e++) p[e] /= Z;
        int i0 = 0;
#pragma unroll
        for (int e = 1; e < E_NUM; e++) if (p[e] > p[i0]) i0 = e;
        int i1 = (i0 == 0) ? 1 : 0;
#pragma unroll
        for (int e = 0; e < E_NUM; e++) if (e != i0 && p[e] > p[i1]) i1 = e;
        float s = p[i0] + p[i1] + 1e-9f;
        g_top_idx[2 * t + 0] = i0; g_top_w[2 * t + 0] = p[i0] / s;
        g_top_idx[2 * t + 1] = i1; g_top_w[2 * t + 1] = p[i1] / s;
        atomicAdd(&g_counts[i0], 1);
        atomicAdd(&g_counts[i1], 1);
    }
}

__global__ void scan_kernel() {
    if (threadIdx.x == 0) {
        int o = 0;
        for (int e = 0; e < E_NUM; e++) {
            g_aoff[e] = o; g_cursor[e] = o;
            int a = (g_counts[e] + 127) & ~127;
            for (int t = o / 128; t < (o + a) / 128; t++) g_tile_e[t] = e;
            o += a;
        }
        for (int t = o / 128; t < MTILES; t++) g_tile_e[t] = E_NUM - 1;
    }
}

__global__ void scatter_kernel() {
    int t = blockIdx.x * blockDim.x + threadIdx.x;
    if (t >= T_TOK) return;
#pragma unroll
    for (int k = 0; k < 2; k++) {
        int e = g_top_idx[2 * t + k];
        int row = atomicAdd(&g_cursor[e], 1);
        g_rowtok[row] = t;
        g_rowgate[row] = g_top_w[2 * t + k];
        g_tokrow[2 * t + k] = row;
    }
}

// ---------------- fp16 conversions ----------------
__global__ void convert_w_kernel(const float* __restrict__ w, __half* __restrict__ hi, int n4) {
    int i = blockIdx.x * blockDim.x + threadIdx.x;
    if (i >= n4) return;
    float4 v = ((const float4*)w)[i];
    __half h0 = __float2half_rn(v.x), h1 = __float2half_rn(v.y);
    __half h2 = __float2half_rn(v.z), h3 = __float2half_rn(v.w);
    uint2 h;
    h.x = (uint32_t)__half_as_ushort(h0) | ((uint32_t)__half_as_ushort(h1) << 16);
    h.y = (uint32_t)__half_as_ushort(h2) | ((uint32_t)__half_as_ushort(h3) << 16);
    ((uint2*)hi)[i] = h;
}

__global__ void gather_kernel(const float* __restrict__ x) {
    int idx = blockIdx.x * blockDim.x + threadIdx.x;   // over PROWS * 256
    int r = idx >> 8, c4 = idx & 255;
    int t = g_rowtok[r];
    float4 v = make_float4(0.f, 0.f, 0.f, 0.f);
    if (t >= 0) v = ((const float4*)x)[(size_t)t * 256 + c4];
    __half h0 = __float2half_rn(v.x), h1 = __float2half_rn(v.y);
    __half h2 = __float2half_rn(v.z), h3 = __float2half_rn(v.w);
    uint2 h;
    h.x = (uint32_t)__half_as_ushort(h0) | ((uint32_t)__half_as_ushort(h1) << 16);
    h.y = (uint32_t)__half_as_ushort(h2) | ((uint32_t)__half_as_ushort(h3) << 16);
    ((uint2*)g_a)[(size_t)r * 256 + c4] = h;
}

// ------- mma.sync GEMM: CTA 128x256, 8 warps 64x64, fragment double-buffer -----
// MODE 0: H = gelu(A@W1^T + b1) -> fp16 (+ converts a W2 slice at kernel top).
// MODE 1: Y = (A@W2^T + b2)*gate -> fp32.
template <int MODE, int KDIM>
__global__ void __launch_bounds__(256, 1) gemm_mma(
    const __half* __restrict__ Ah, const __half* __restrict__ Bh,
    const float* __restrict__ bias, int NDIM,
    const float* __restrict__ wsrc, __half* __restrict__ wdst, int wn4) {

    int tid  = threadIdx.x;
    int lane = tid & 31, wid = tid >> 5;

    if (MODE == 0) {
        int nblk   = gridDim.x * gridDim.y;
        int bid    = blockIdx.y * gridDim.x + blockIdx.x;
        int stride = nblk * 256;
        for (int i = bid * 256 + tid; i < wn4; i += stride) {
            float4 v = ((const float4*)wsrc)[i];
            __half h0 = __float2half_rn(v.x), h1 = __float2half_rn(v.y);
            __half h2 = __float2half_rn(v.z), h3 = __float2half_rn(v.w);
            uint2 h;
            h.x = (uint32_t)__half_as_ushort(h0) | ((uint32_t)__half_as_ushort(h1) << 16);
            h.y = (uint32_t)__half_as_ushort(h2) | ((uint32_t)__half_as_ushort(h3) << 16);
            ((uint2*)wdst)[i] = h;
        }
    }

    int e  = g_tile_e[blockIdx.y];
    int m0 = blockIdx.y * 128;
    if (m0 >= g_aoff[e] + g_counts[e]) return;
    int n0    = blockIdx.x * NTILE;
    int bbase = e * NDIM + n0;

    extern __shared__ char smem[];
    uint32_t sb  = s2u(smem);
    int wm = wid >> 2, wn = wid & 3;   // 2x4 warp grid, warp tile 64x64

    const int NCH = KDIM / KCH;

    auto load_stage = [&](int c, int st) {
        int k0 = c * KCH;
        uint32_t stg = sb + st * STAGE_B;
#pragma unroll
        for (int i = 0; i < 12; i++) {              // (1024 A + 2048 B chunks) / 256 thr
            int ci = i * 256 + tid;
            uint32_t dst;
            const __half* src;
            if (ci < 1024) {
                int row = ci >> 3, c16 = ci & 7;
                dst = stg + row * (LDSE * 2) + c16 * 16;
                src = Ah + (size_t)(m0 + row) * KDIM + k0 + c16 * 8;
            } else {
                int bi = ci - 1024;
                int row = bi >> 3, c16 = bi & 7;
                dst = stg + TILE_A + row * (LDSE * 2) + c16 * 16;
                src = Bh + (size_t)(bbase + row) * KDIM + k0 + c16 * 8;
            }
            cpasync16(dst, src);
        }
        cp_commit();
    };

    int aoff = (wm * 64 + (lane & 15)) * LDSE + (lane >> 4) * 8;
    int boff = (wn * 64 + ((lane >> 4) << 3) + (lane & 7)) * LDSE + ((lane >> 3) & 1) * 8;

    float acc[4][8][4];
#pragma unroll
    for (int a = 0; a < 4; a++)
#pragma unroll
        for (int b = 0; b < 8; b++)
#pragma unroll
            for (int q = 0; q < 4; q++) acc[a][b][q] = 0.f;

    load_stage(0, 0);
    load_stage(1, 1);

    uint32_t ah[2][4][4], bh[2][4][4];

    for (int c = 0; c < NCH; c++) {
        if (c + 1 < NCH) asm volatile("cp.async.wait_group 1;" ::: "memory");
        else             asm volatile("cp.async.wait_group 0;" ::: "memory");
        __syncthreads();
        if (c + 2 < NCH) load_stage(c + 2, (c + 2) % NSTAGE);

        uint32_t stg = sb + (c % NSTAGE) * STAGE_B;
        uint32_t aH = stg + aoff * 2;
        uint32_t bH = stg + TILE_A + boff * 2;

        // preload kk=0 fragments
#pragma unroll
        for (int g = 0; g < 4; g++) ldmx4(bh[0][g], bH + g * (16 * LDSE * 2));
#pragma unroll
        for (int f = 0; f < 4; f++) ldmx4(ah[0][f], aH + f * (16 * LDSE * 2));

#pragma unroll
        for (int kk = 0; kk < 4; kk++) {
            int cur = kk & 1, nxt = cur ^ 1;
            if (kk < 3) {
                uint32_t k2 = (kk + 1) * 32;
#pragma unroll
                for (int g = 0; g < 4; g++) ldmx4(bh[nxt][g], bH + g * (16 * LDSE * 2) + k2);
#pragma unroll
                for (int f = 0; f < 4; f++) ldmx4(ah[nxt][f], aH + f * (16 * LDSE * 2) + k2);
            }
#pragma unroll
            for (int mi = 0; mi < 4; mi++)
#pragma unroll
                for (int g = 0; g < 4; g++) {
                    mma16816(acc[mi][g * 2 + 0], ah[cur][mi], &bh[cur][g][0]);
                    mma16816(acc[mi][g * 2 + 1], ah[cur][mi], &bh[cur][g][2]);
                }
        }
    }

    // ---------------- staged epilogue (coalesced stores) ----------------
    __syncthreads();   // pipeline smem free; reuse for staging

    if (MODE == 0) {
        // warp region: 64 rows x HSTG2 (128B data + 16B pad) = 9216 B
        uint32_t wsm = sb + wid * (64 * HSTG2);
#pragma unroll
        for (int mi = 0; mi < 4; mi++)
#pragma unroll
            for (int rr = 0; rr < 2; rr++) {
                int rl = mi * 16 + rr * 8 + (lane >> 2);
#pragma unroll
                for (int ni = 0; ni < 8; ni++) {
                    int cl = ni * 8 + (lane & 3) * 2;
                    int gcol = n0 + wn * 64 + cl;
                    float v0 = acc[mi][ni][rr * 2 + 0] + bias[e * NDIM + gcol];
                    float v1 = acc[mi][ni][rr * 2 + 1] + bias[e * NDIM + gcol + 1];
                    v0 = 0.5f * v0 * (1.f + erff(v0 * 0.70710678118654752f));
                    v1 = 0.5f * v1 * (1.f + erff(v1 * 0.70710678118654752f));
                    __half h0 = __float2half_rn(v0), h1 = __float2half_rn(v1);
                    uint32_t hp = (uint32_t)__half_as_ushort(h0) | ((uint32_t)__half_as_ushort(h1) << 16);
                    asm volatile("st.shared.b32 [%0], %1;" :: "r"(wsm + rl * HSTG2 + cl * 2), "r"(hp));
                }
            }
        __syncwarp();
        // 64 rows x 8 segs(16B) = 512 vectors / 32 lanes = 16 iters
#pragma unroll
        for (int i = 0; i < 16; i++) {
            int rl = i * 4 + (lane >> 3), seg = lane & 7;
            uint4 v;
            asm volatile("ld.shared.v4.b32 {%0,%1,%2,%3}, [%4];"
                         : "=r"(v.x), "=r"(v.y), "=r"(v.z), "=r"(v.w)
                         : "r"(wsm + rl * HSTG2 + seg * 16));
            int r = m0 + wm * 64 + rl;
            *(uint4*)&g_h[(size_t)r * FF_DIM + n0 + wn * 64 + seg * 8] = v;
        }
    } else {
        // warp region: 64 rows x YSTG2 (256B data + 16B pad) = 17408 B
        uint32_t wsm = sb + wid * (64 * YSTG2);
#pragma unroll
        for (int mi = 0; mi < 4; mi++)
#pragma unroll
            for (int rr = 0; rr < 2; rr++) {
                int rl = mi * 16 + rr * 8 + (lane >> 2);
                int r  = m0 + wm * 64 + rl;
                float gate = g_rowgate[r];
#pragma unroll
                for (int ni = 0; ni < 8; ni++) {
                    int cl = ni * 8 + (lane & 3) * 2;
                    int gcol = n0 + wn * 64 + cl;
                    float v0 = (acc[mi][ni][rr * 2 + 0] + bias[e * NDIM + gcol]) * gate;
                    float v1 = (acc[mi][ni][rr * 2 + 1] + bias[e * NDIM + gcol + 1]) * gate;
                    asm volatile("st.shared.v2.f32 [%0], {%1,%2};"
                                 :: "r"(wsm + rl * YSTG2 + cl * 4), "f"(v0), "f"(v1));
                }
            }
        __syncwarp();
        // 64 rows x 16 segs(16B) = 1024 vectors / 32 lanes = 32 iters
#pragma unroll
        for (int i = 0; i < 32; i++) {
            int rl = i * 2 + (lane >> 4), seg = lane & 15;
            uint4 v;
            asm volatile("ld.shared.v4.b32 {%0,%1,%2,%3}, [%4];"
                         : "=r"(v.x), "=r"(v.y), "=r"(v.z), "=r"(v.w)
                         : "r"(wsm + rl * YSTG2 + seg * 16));
            int r = m0 + wm * 64 + rl;
            *(uint4*)&g_y[(size_t)r * C_DIM + n0 + wn * 64 + seg * 4] = v;
        }
    }
}

// ---------------- combine ----------------
__global__ void combine_kernel(float* __restrict__ out) {
    int i = blockIdx.x * blockDim.x + threadIdx.x;   // T_TOK * 256
    if (i >= T_TOK * (C_DIM / 4)) return;
    int t = i >> 8, c4 = i & 255;
    int r0 = g_tokrow[2 * t + 0];
    int r1 = g_tokrow[2 * t + 1];
    const float4* y4 = (const float4*)g_y;
    float4 a = y4[(size_t)r0 * 256 + c4];
    float4 b = y4[(size_t)r1 * 256 + c4];
    ((float4*)out)[i] = make_float4(a.x + b.x, a.y + b.y, a.z + b.z, a.w + b.w);
}

// ---------------- host ----------------
extern "C" void kernel_launch(void* const* d_in, const int* in_sizes, int n_in,
                              void* d_out, int out_size) {
    const float* x  = (const float*)d_in[0];
    const float* rw = (const float*)d_in[1];
    const float* w1 = (const float*)d_in[2];
    const float* b1 = (const float*)d_in[3];
    const float* w2 = (const float*)d_in[4];
    const float* b2 = (const float*)d_in[5];
    float* out = (float*)d_out;

    void *pA, *pW1, *pW2, *pH;
    cudaGetSymbolAddress(&pA, g_a);
    cudaGetSymbolAddress(&pW1, g_w1);
    cudaGetSymbolAddress(&pW2, g_w2);
    cudaGetSymbolAddress(&pH, g_h);

    cudaFuncSetAttribute(gemm_mma<0, C_DIM>,  cudaFuncAttributeMaxDynamicSharedMemorySize, SMEM_TOTAL);
    cudaFuncSetAttribute(gemm_mma<1, FF_DIM>, cudaFuncAttributeMaxDynamicSharedMemorySize, SMEM_TOTAL);

    init_kernel<<<PROWS / 256, 256>>>();
    router_kernel<<<(T_TOK * 32) / 256, 256>>>(x, rw);
    scan_kernel<<<1, 1>>>();
    scatter_kernel<<<T_TOK / 256, 256>>>();
    gather_kernel<<<PROWS, 256>>>(x);

    int n4w = E_NUM * FF_DIM * C_DIM / 4;
    convert_w_kernel<<<n4w / 256, 256>>>(w1, (__half*)pW1, n4w);
    // W2 conversion fused into gemm1's CTAs

    dim3 g1(FF_DIM / NTILE, MTILES);   // (16, 72)
    gemm_mma<0, C_DIM><<<g1, 256, SMEM_TOTAL>>>(
        (const __half*)pA, (const __half*)pW1, b1, FF_DIM,
        w2, (__half*)pW2, n4w);

    dim3 g2(C_DIM / NTILE, MTILES);    // (4, 72)
    gemm_mma<1, FF_DIM><<<g2, 256, SMEM_TOTAL>>>(
        (const __half*)pH, (const __half*)pW2, b2, C_DIM,
        nullptr, nullptr, 0);

    combine_kernel<<<(T_TOK * (C_DIM / 4)) / 256, 256>>>(out);
}

// round 15
// speedup vs baseline: 1.1380x; 1.1380x over previous
#include <cuda_runtime.h>
#include <cuda_fp16.h>
#include <math.h>
#include <stdint.h>

#define T_TOK   4096
#define C_DIM   1024
#define FF_DIM  4096
#define E_NUM   8
#define PROWS   9216            // 8192 rows + per-expert pad to 128
#define MTILES  (PROWS/128)     // 72

#define KCH     64              // K columns per pipeline chunk
#define LDSE    72              // padded fp16 elems per 64-elem row (144B stride)
#define TILE_B  (128*LDSE*2)    // 18432 bytes per tile
#define STAGE_B (2*TILE_B)      // A + B = 36864
#define NSTAGE  3
#define SMEM_PIPE  (NSTAGE*STAGE_B)   // 110592
#define SMEM_TOTAL (SMEM_PIPE + 512)  // + rowtok table; 111104 -> still 2 CTAs/SM

// epilogue staging strides (16B-aligned)
#define HSTG    80              // bytes per row, H staging
#define YSTG    144             // bytes per row, Y staging

#define XCNT   (T_TOK*C_DIM/4)            // 1048576 float4
#define N4W    (E_NUM*FF_DIM*C_DIM/4)     // 8388608 float4

// ---------------- scratch (static device globals; no allocation) ----------------
__device__ int   g_counts[E_NUM];
__device__ int   g_aoff[E_NUM];
__device__ int   g_cursor[E_NUM];
__device__ int   g_tile_e[MTILES];
__device__ int   g_top_idx[T_TOK * 2];
__device__ float g_top_w[T_TOK * 2];
__device__ int   g_rowtok[PROWS];
__device__ float g_rowgate[PROWS];
__device__ int   g_tokrow[T_TOK * 2];

__device__ __align__(128) __half g_xh[(size_t)T_TOK * C_DIM];
__device__ __align__(128) __half g_w1[(size_t)E_NUM * FF_DIM * C_DIM];
__device__ __align__(128) __half g_w2[(size_t)E_NUM * C_DIM * FF_DIM];
__device__ __align__(128) __half g_h[(size_t)PROWS * FF_DIM];
__device__ __align__(128) float  g_y[(size_t)PROWS * C_DIM];

// ---------------- PTX helpers (baseline-PTX only) ----------------
__device__ __forceinline__ uint32_t s2u(const void* p) {
    uint32_t a;
    asm("{ .reg .u64 t; cvta.to.shared.u64 t, %1; cvt.u32.u64 %0, t; }" : "=r"(a) : "l"(p));
    return a;
}
__device__ __forceinline__ void cpasync16(uint32_t dst, const void* src) {
    asm volatile("cp.async.cg.shared.global [%0], [%1], 16;" :: "r"(dst), "l"(src));
}
__device__ __forceinline__ void cp_commit() {
    asm volatile("cp.async.commit_group;" ::: "memory");
}
__device__ __forceinline__ void ldmx4(uint32_t* r, uint32_t addr) {
    asm volatile("ldmatrix.sync.aligned.m8n8.x4.shared.b16 {%0,%1,%2,%3}, [%4];"
                 : "=r"(r[0]), "=r"(r[1]), "=r"(r[2]), "=r"(r[3]) : "r"(addr));
}
__device__ __forceinline__ void mma16816(float* c, const uint32_t* a, const uint32_t* b) {
    asm volatile("mma.sync.aligned.m16n8k16.row.col.f32.f16.f16.f32 "
                 "{%0,%1,%2,%3}, {%4,%5,%6,%7}, {%8,%9}, {%0,%1,%2,%3};"
                 : "+f"(c[0]), "+f"(c[1]), "+f"(c[2]), "+f"(c[3])
                 : "r"(a[0]), "r"(a[1]), "r"(a[2]), "r"(a[3]), "r"(b[0]), "r"(b[1]));
}
__device__ __forceinline__ uint2 pack4h(float4 v) {
    __half h0 = __float2half_rn(v.x), h1 = __float2half_rn(v.y);
    __half h2 = __float2half_rn(v.z), h3 = __float2half_rn(v.w);
    uint2 h;
    h.x = (uint32_t)__half_as_ushort(h0) | ((uint32_t)__half_as_ushort(h1) << 16);
    h.y = (uint32_t)__half_as_ushort(h2) | ((uint32_t)__half_as_ushort(h3) << 16);
    return h;
}

// ---------------- routing ----------------
__global__ void init_kernel() {
    int i = blockIdx.x * blockDim.x + threadIdx.x;
    if (i < E_NUM) g_counts[i] = 0;
    if (i < PROWS) g_rowtok[i] = -1;
}

__global__ void router_kernel(const float* __restrict__ x, const float* __restrict__ rw) {
    int gtid = blockIdx.x * blockDim.x + threadIdx.x;
    int t = gtid >> 5, lane = threadIdx.x & 31;
    if (t >= T_TOK) return;
    const float4* xr4 = (const float4*)(x + (size_t)t * C_DIM);
    const float4* rw4 = (const float4*)rw;
    float acc[E_NUM];
#pragma unroll
    for (int e = 0; e < E_NUM; e++) acc[e] = 0.f;
    for (int c4 = lane; c4 < C_DIM / 4; c4 += 32) {
        float4 xv = xr4[c4];
#pragma unroll
        for (int e = 0; e < E_NUM; e++) {
            float4 wv = rw4[e * (C_DIM / 4) + c4];
            acc[e] += xv.x * wv.x + xv.y * wv.y + xv.z * wv.z + xv.w * wv.w;
        }
    }
#pragma unroll
    for (int e = 0; e < E_NUM; e++)
#pragma unroll
        for (int o = 16; o; o >>= 1) acc[e] += __shfl_xor_sync(0xFFFFFFFFu, acc[e], o);
    if (lane == 0) {
        float m = acc[0];
#pragma unroll
        for (int e = 1; e < E_NUM; e++) m = fmaxf(m, acc[e]);
        float p[E_NUM], Z = 0.f;
#pragma unroll
        for (int e = 0; e < E_NUM; e++) { p[e] = expf(acc[e] - m); Z += p[e]; }
#pragma unroll
        for (int e = 0; e < E_NUM; e++) p[e] /= Z;
        int i0 = 0;
#pragma unroll
        for (int e = 1; e < E_NUM; e++) if (p[e] > p[i0]) i0 = e;
        int i1 = (i0 == 0) ? 1 : 0;
#pragma unroll
        for (int e = 0; e < E_NUM; e++) if (e != i0 && p[e] > p[i1]) i1 = e;
        float s = p[i0] + p[i1] + 1e-9f;
        g_top_idx[2 * t + 0] = i0; g_top_w[2 * t + 0] = p[i0] / s;
        g_top_idx[2 * t + 1] = i1; g_top_w[2 * t + 1] = p[i1] / s;
        atomicAdd(&g_counts[i0], 1);
        atomicAdd(&g_counts[i1], 1);
    }
}

__global__ void scan_kernel() {
    if (threadIdx.x == 0) {
        int o = 0;
        for (int e = 0; e < E_NUM; e++) {
            g_aoff[e] = o; g_cursor[e] = o;
            int a = (g_counts[e] + 127) & ~127;
            for (int t = o / 128; t < (o + a) / 128; t++) g_tile_e[t] = e;
            o += a;
        }
        for (int t = o / 128; t < MTILES; t++) g_tile_e[t] = E_NUM - 1;
    }
}

__global__ void scatter_kernel() {
    int t = blockIdx.x * blockDim.x + threadIdx.x;
    if (t >= T_TOK) return;
#pragma unroll
    for (int k = 0; k < 2; k++) {
        int e = g_top_idx[2 * t + k];
        int row = atomicAdd(&g_cursor[e], 1);
        g_rowtok[row] = t;
        g_rowgate[row] = g_top_w[2 * t + k];
        g_tokrow[2 * t + k] = row;
    }
}

// ---------------- prep: x -> fp16 tokens, W1 -> fp16 (one kernel) ----------------
__global__ void prep_kernel(const float* __restrict__ x, const float* __restrict__ w1) {
    int i = blockIdx.x * blockDim.x + threadIdx.x;
    if (i < XCNT) {
        ((uint2*)g_xh)[i] = pack4h(((const float4*)x)[i]);
    } else {
        int j = i - XCNT;
        if (j < N4W) ((uint2*)g_w1)[j] = pack4h(((const float4*)w1)[j]);
    }
}

// ---------------- mma.sync GEMM (R13 core + indirect A gather in MODE 0) --------
// MODE 0: H = gelu(X[rowtok]@W1^T + b1) -> fp16 (+ converts a W2 slice at top).
// MODE 1: Y = (H@W2^T + b2)*gate -> fp32.
template <int MODE, int KDIM>
__global__ void __launch_bounds__(256, 2) gemm_mma(
    const __half* __restrict__ Ah, const __half* __restrict__ Bh,
    const float* __restrict__ bias, int NDIM,
    const float* __restrict__ wsrc, __half* __restrict__ wdst, int wn4) {

    int tid  = threadIdx.x;
    int lane = tid & 31, wid = tid >> 5;

    // fused W2 conversion slice (MODE 0 only; before any early return)
    if (MODE == 0) {
        int nblk   = gridDim.x * gridDim.y;
        int bid    = blockIdx.y * gridDim.x + blockIdx.x;
        int stride = nblk * 256;
        for (int i = bid * 256 + tid; i < wn4; i += stride)
            ((uint2*)wdst)[i] = pack4h(((const float4*)wsrc)[i]);
    }

    int e  = g_tile_e[blockIdx.y];
    int m0 = blockIdx.y * 128;
    if (m0 >= g_aoff[e] + g_counts[e]) return;
    int n0    = blockIdx.x * 128;
    int bbase = e * NDIM + n0;

    extern __shared__ char smem[];
    uint32_t sb = s2u(smem);
    int* rowtok_s = (int*)(smem + SMEM_PIPE);
    int wm = wid >> 2, wn = wid & 3;   // 2x4 warp grid, warp tile 64x32

    if (MODE == 0) {
        if (tid < 128) {
            int t = g_rowtok[m0 + tid];
            rowtok_s[tid] = (t < 0) ? 0 : t;   // padded rows -> token 0 (discarded)
        }
        __syncthreads();
    }

    const int NCH = KDIM / KCH;

    auto load_stage = [&](int c, int st) {
        int k0 = c * KCH;
        uint32_t stg = sb + st * STAGE_B;
#pragma unroll
        for (int i = 0; i < 8; i++) {               // 2 tiles * 1024 chunks / 256 thr
            int ci = i * 256 + tid;
            int tile = ci >> 10, rc = ci & 1023, row = rc >> 3, c16 = rc & 7;
            uint32_t dst = stg + tile * TILE_B + row * (LDSE * 2) + c16 * 16;
            const __half* src;
            if (tile == 0) {
                if (MODE == 0) src = Ah + (size_t)rowtok_s[row] * KDIM;
                else           src = Ah + (size_t)(m0 + row) * KDIM;
            } else {
                src = Bh + (size_t)(bbase + row) * KDIM;
            }
            cpasync16(dst, src + k0 + c16 * 8);
        }
        cp_commit();
    };

    int aoff = (wm * 64 + (lane & 15)) * LDSE + (lane >> 4) * 8;
    int boff = (wn * 32 + ((lane >> 4) << 3) + (lane & 7)) * LDSE + ((lane >> 3) & 1) * 8;

    float acc[4][4][4];
#pragma unroll
    for (int a = 0; a < 4; a++)
#pragma unroll
        for (int b = 0; b < 4; b++)
#pragma unroll
            for (int q = 0; q < 4; q++) acc[a][b][q] = 0.f;

    load_stage(0, 0);
    load_stage(1, 1);

    for (int c = 0; c < NCH; c++) {
        if (c + 1 < NCH) asm volatile("cp.async.wait_group 1;" ::: "memory");
        else             asm volatile("cp.async.wait_group 0;" ::: "memory");
        __syncthreads();
        if (c + 2 < NCH) load_stage(c + 2, (c + 2) % NSTAGE);

        uint32_t stg = sb + (c % NSTAGE) * STAGE_B;
        uint32_t aH = stg + aoff * 2;
        uint32_t bH = stg + TILE_B + boff * 2;

#pragma unroll
        for (int kk = 0; kk < 4; kk++) {
            uint32_t k2 = kk * 32;   // 16 fp16 = 32 bytes
            uint32_t ah[4][4], bh[2][4];
#pragma unroll
            for (int g = 0; g < 2; g++) ldmx4(bh[g], bH + g * (16 * LDSE * 2) + k2);
#pragma unroll
            for (int f = 0; f < 4; f++) ldmx4(ah[f], aH + f * (16 * LDSE * 2) + k2);
#pragma unroll
            for (int mi = 0; mi < 4; mi++)
#pragma unroll
                for (int g = 0; g < 2; g++) {
                    mma16816(acc[mi][g * 2 + 0], ah[mi], &bh[g][0]);
                    mma16816(acc[mi][g * 2 + 1], ah[mi], &bh[g][2]);
                }
        }
    }

    // ---------------- staged epilogue (coalesced stores) ----------------
    __syncthreads();   // pipeline smem no longer needed; reuse for staging

    if (MODE == 0) {
        uint32_t wsm = sb + wid * (64 * HSTG);
#pragma unroll
        for (int mi = 0; mi < 4; mi++)
#pragma unroll
            for (int rr = 0; rr < 2; rr++) {
                int rl = mi * 16 + rr * 8 + (lane >> 2);
#pragma unroll
                for (int ni = 0; ni < 4; ni++) {
                    int cl = ni * 8 + (lane & 3) * 2;
                    int gcol = n0 + wn * 32 + cl;
                    float v0 = acc[mi][ni][rr * 2 + 0] + bias[e * NDIM + gcol];
                    float v1 = acc[mi][ni][rr * 2 + 1] + bias[e * NDIM + gcol + 1];
                    v0 = 0.5f * v0 * (1.f + erff(v0 * 0.70710678118654752f));
                    v1 = 0.5f * v1 * (1.f + erff(v1 * 0.70710678118654752f));
                    __half h0 = __float2half_rn(v0), h1 = __float2half_rn(v1);
                    uint32_t hp = (uint32_t)__half_as_ushort(h0) | ((uint32_t)__half_as_ushort(h1) << 16);
                    asm volatile("st.shared.b32 [%0], %1;" :: "r"(wsm + rl * HSTG + cl * 2), "r"(hp));
                }
            }
        __syncwarp();
#pragma unroll
        for (int i = 0; i < 8; i++) {
            int rl = i * 8 + (lane >> 2), seg = lane & 3;
            uint4 v;
            asm volatile("ld.shared.v4.b32 {%0,%1,%2,%3}, [%4];"
                         : "=r"(v.x), "=r"(v.y), "=r"(v.z), "=r"(v.w)
                         : "r"(wsm + rl * HSTG + seg * 16));
            int r = m0 + wm * 64 + rl;
            *(uint4*)&g_h[(size_t)r * FF_DIM + n0 + wn * 32 + seg * 8] = v;
        }
    } else {
        uint32_t wsm = sb + wid * (64 * YSTG);
#pragma unroll
        for (int mi = 0; mi < 4; mi++)
#pragma unroll
            for (int rr = 0; rr < 2; rr++) {
                int rl = mi * 16 + rr * 8 + (lane >> 2);
                int r  = m0 + wm * 64 + rl;
                float gate = g_rowgate[r];
#pragma unroll
                for (int ni = 0; ni < 4; ni++) {
                    int cl = ni * 8 + (lane & 3) * 2;
                    int gcol = n0 + wn * 32 + cl;
                    float v0 = (acc[mi][ni][rr * 2 + 0] + bias[e * NDIM + gcol]) * gate;
                    float v1 = (acc[mi][ni][rr * 2 + 1] + bias[e * NDIM + gcol + 1]) * gate;
                    asm volatile("st.shared.v2.f32 [%0], {%1,%2};"
                                 :: "r"(wsm + rl * YSTG + cl * 4), "f"(v0), "f"(v1));
                }
            }
        __syncwarp();
#pragma unroll
        for (int i = 0; i < 16; i++) {
            int rl = i * 4 + (lane >> 3), seg = lane & 7;
            uint4 v;
            asm volatile("ld.shared.v4.b32 {%0,%1,%2,%3}, [%4];"
                         : "=r"(v.x), "=r"(v.y), "=r"(v.z), "=r"(v.w)
                         : "r"(wsm + rl * YSTG + seg * 16));
            int r = m0 + wm * 64 + rl;
            *(uint4*)&g_y[(size_t)r * C_DIM + n0 + wn * 32 + seg * 4] = v;
        }
    }
}

// ---------------- combine ----------------
__global__ void combine_kernel(float* __restrict__ out) {
    int i = blockIdx.x * blockDim.x + threadIdx.x;   // T_TOK * 256
    if (i >= T_TOK * (C_DIM / 4)) return;
    int t = i >> 8, c4 = i & 255;
    int r0 = g_tokrow[2 * t + 0];
    int r1 = g_tokrow[2 * t + 1];
    const float4* y4 = (const float4*)g_y;
    float4 a = y4[(size_t)r0 * 256 + c4];
    float4 b = y4[(size_t)r1 * 256 + c4];
    ((float4*)out)[i] = make_float4(a.x + b.x, a.y + b.y, a.z + b.z, a.w + b.w);
}

// ---------------- host ----------------
extern "C" void kernel_launch(void* const* d_in, const int* in_sizes, int n_in,
                              void* d_out, int out_size) {
    const float* x  = (const float*)d_in[0];
    const float* rw = (const float*)d_in[1];
    const float* w1 = (const float*)d_in[2];
    const float* b1 = (const float*)d_in[3];
    const float* w2 = (const float*)d_in[4];
    const float* b2 = (const float*)d_in[5];
    float* out = (float*)d_out;

    void *pX, *pW1, *pW2, *pH;
    cudaGetSymbolAddress(&pX, g_xh);
    cudaGetSymbolAddress(&pW1, g_w1);
    cudaGetSymbolAddress(&pW2, g_w2);
    cudaGetSymbolAddress(&pH, g_h);

    cudaFuncSetAttribute(gemm_mma<0, C_DIM>,  cudaFuncAttributeMaxDynamicSharedMemorySize, SMEM_TOTAL);
    cudaFuncSetAttribute(gemm_mma<1, FF_DIM>, cudaFuncAttributeMaxDynamicSharedMemorySize, SMEM_TOTAL);

    // launch order keeps gemm1 as the 6th launch (ncu -s 5 -c 1 captures it)
    init_kernel<<<PROWS / 256, 256>>>();                                   // 1
    router_kernel<<<(T_TOK * 32) / 256, 256>>>(x, rw);                     // 2
    scan_kernel<<<1, 1>>>();                                               // 3
    scatter_kernel<<<T_TOK / 256, 256>>>();                                // 4
    prep_kernel<<<(XCNT + N4W) / 256, 256>>>(x, w1);                       // 5

    dim3 g1(FF_DIM / 128, MTILES);   // (32, 72)
    gemm_mma<0, C_DIM><<<g1, 256, SMEM_TOTAL>>>(                           // 6
        (const __half*)pX, (const __half*)pW1, b1, FF_DIM,
        w2, (__half*)pW2, N4W);

    dim3 g2(C_DIM / 128, MTILES);    // (8, 72)
    gemm_mma<1, FF_DIM><<<g2, 256, SMEM_TOTAL>>>(                          // 7
        (const __half*)pH, (const __half*)pW2, b2, C_DIM,
        nullptr, nullptr, 0);

    combine_kernel<<<(T_TOK * (C_DIM / 4)) / 256, 256>>>(out);             // 8
}

// round 16
// speedup vs baseline: 1.1477x; 1.0085x over previous
#include <cuda_runtime.h>
#include <cuda_fp16.h>
#include <math.h>
#include <stdint.h>

#define T_TOK   4096
#define C_DIM   1024
#define FF_DIM  4096
#define E_NUM   8
#define PROWS   9216            // 8192 rows + per-expert pad to 128
#define MTILES  (PROWS/128)     // 72

#define KCH     64              // K columns per pipeline chunk
#define LDSE    72              // padded fp16 elems per 64-elem row (144B stride)
#define TILE_B  (128*LDSE*2)    // 18432 bytes per tile
#define STAGE_B (2*TILE_B)      // A + B = 36864
#define NSTAGE  3
#define SMEM_PIPE  (NSTAGE*STAGE_B)   // 110592
#define SMEM_TOTAL (SMEM_PIPE + 512)  // + rowtok table; 111104 -> 2 CTAs/SM

// epilogue staging stride (16B-aligned)
#define HSTG    80              // bytes per row, H staging

#define XCNT   (T_TOK*C_DIM/4)            // 1048576 float4
#define N4W    (E_NUM*FF_DIM*C_DIM/4)     // 8388608 float4

// ---------------- scratch (static device globals; no allocation) ----------------
__device__ int   g_counts[E_NUM];
__device__ int   g_aoff[E_NUM];
__device__ int   g_cursor[E_NUM];
__device__ int   g_tile_e[MTILES];
__device__ int   g_top_idx[T_TOK * 2];
__device__ float g_top_w[T_TOK * 2];
__device__ int   g_rowtok[PROWS];
__device__ float g_rowgate[PROWS];
__device__ int   g_tokrow[T_TOK * 2];

__device__ __align__(128) __half g_xh[(size_t)T_TOK * C_DIM];
__device__ __align__(128) __half g_w1[(size_t)E_NUM * FF_DIM * C_DIM];
__device__ __align__(128) __half g_w2[(size_t)E_NUM * C_DIM * FF_DIM];
__device__ __align__(128) __half g_h[(size_t)PROWS * FF_DIM];

// ---------------- PTX helpers (baseline-PTX only) ----------------
__device__ __forceinline__ uint32_t s2u(const void* p) {
    uint32_t a;
    asm("{ .reg .u64 t; cvta.to.shared.u64 t, %1; cvt.u32.u64 %0, t; }" : "=r"(a) : "l"(p));
    return a;
}
__device__ __forceinline__ void cpasync16(uint32_t dst, const void* src) {
    asm volatile("cp.async.cg.shared.global [%0], [%1], 16;" :: "r"(dst), "l"(src));
}
__device__ __forceinline__ void cp_commit() {
    asm volatile("cp.async.commit_group;" ::: "memory");
}
__device__ __forceinline__ void ldmx4(uint32_t* r, uint32_t addr) {
    asm volatile("ldmatrix.sync.aligned.m8n8.x4.shared.b16 {%0,%1,%2,%3}, [%4];"
                 : "=r"(r[0]), "=r"(r[1]), "=r"(r[2]), "=r"(r[3]) : "r"(addr));
}
__device__ __forceinline__ void mma16816(float* c, const uint32_t* a, const uint32_t* b) {
    asm volatile("mma.sync.aligned.m16n8k16.row.col.f32.f16.f16.f32 "
                 "{%0,%1,%2,%3}, {%4,%5,%6,%7}, {%8,%9}, {%0,%1,%2,%3};"
                 : "+f"(c[0]), "+f"(c[1]), "+f"(c[2]), "+f"(c[3])
                 : "r"(a[0]), "r"(a[1]), "r"(a[2]), "r"(a[3]), "r"(b[0]), "r"(b[1]));
}
__device__ __forceinline__ uint2 pack4h(float4 v) {
    __half h0 = __float2half_rn(v.x), h1 = __float2half_rn(v.y);
    __half h2 = __float2half_rn(v.z), h3 = __float2half_rn(v.w);
    uint2 h;
    h.x = (uint32_t)__half_as_ushort(h0) | ((uint32_t)__half_as_ushort(h1) << 16);
    h.y = (uint32_t)__half_as_ushort(h2) | ((uint32_t)__half_as_ushort(h3) << 16);
    return h;
}

// ---------------- routing ----------------
__global__ void init_kernel() {
    int i = blockIdx.x * blockDim.x + threadIdx.x;
    if (i < E_NUM) g_counts[i] = 0;
    if (i < PROWS) g_rowtok[i] = -1;
}

__global__ void router_kernel(const float* __restrict__ x, const float* __restrict__ rw) {
    int gtid = blockIdx.x * blockDim.x + threadIdx.x;
    int t = gtid >> 5, lane = threadIdx.x & 31;
    if (t >= T_TOK) return;
    const float4* xr4 = (const float4*)(x + (size_t)t * C_DIM);
    const float4* rw4 = (const float4*)rw;
    float acc[E_NUM];
#pragma unroll
    for (int e = 0; e < E_NUM; e++) acc[e] = 0.f;
    for (int c4 = lane; c4 < C_DIM / 4; c4 += 32) {
        float4 xv = xr4[c4];
#pragma unroll
        for (int e = 0; e < E_NUM; e++) {
            float4 wv = rw4[e * (C_DIM / 4) + c4];
            acc[e] += xv.x * wv.x + xv.y * wv.y + xv.z * wv.z + xv.w * wv.w;
        }
    }
#pragma unroll
    for (int e = 0; e < E_NUM; e++)
#pragma unroll
        for (int o = 16; o; o >>= 1) acc[e] += __shfl_xor_sync(0xFFFFFFFFu, acc[e], o);
    if (lane == 0) {
        float m = acc[0];
#pragma unroll
        for (int e = 1; e < E_NUM; e++) m = fmaxf(m, acc[e]);
        float p[E_NUM], Z = 0.f;
#pragma unroll
        for (int e = 0; e < E_NUM; e++) { p[e] = expf(acc[e] - m); Z += p[e]; }
#pragma unroll
        for (int e = 0; e < E_NUM; e++) p[e] /= Z;
        int i0 = 0;
#pragma unroll
        for (int e = 1; e < E_NUM; e++) if (p[e] > p[i0]) i0 = e;
        int i1 = (i0 == 0) ? 1 : 0;
#pragma unroll
        for (int e = 0; e < E_NUM; e++) if (e != i0 && p[e] > p[i1]) i1 = e;
        float s = p[i0] + p[i1] + 1e-9f;
        g_top_idx[2 * t + 0] = i0; g_top_w[2 * t + 0] = p[i0] / s;
        g_top_idx[2 * t + 1] = i1; g_top_w[2 * t + 1] = p[i1] / s;
        atomicAdd(&g_counts[i0], 1);
        atomicAdd(&g_counts[i1], 1);
    }
}

__global__ void scan_kernel() {
    if (threadIdx.x == 0) {
        int o = 0;
        for (int e = 0; e < E_NUM; e++) {
            g_aoff[e] = o; g_cursor[e] = o;
            int a = (g_counts[e] + 127) & ~127;
            for (int t = o / 128; t < (o + a) / 128; t++) g_tile_e[t] = e;
            o += a;
        }
        for (int t = o / 128; t < MTILES; t++) g_tile_e[t] = E_NUM - 1;
    }
}

__global__ void scatter_kernel() {
    int t = blockIdx.x * blockDim.x + threadIdx.x;
    if (t >= T_TOK) return;
#pragma unroll
    for (int k = 0; k < 2; k++) {
        int e = g_top_idx[2 * t + k];
        int row = atomicAdd(&g_cursor[e], 1);
        g_rowtok[row] = t;
        g_rowgate[row] = g_top_w[2 * t + k];
        g_tokrow[2 * t + k] = row;
    }
}

// ---- prep: x -> fp16, W1 -> fp16, zero out (one kernel, three segments) --------
__global__ void prep_kernel(const float* __restrict__ x, const float* __restrict__ w1,
                            float* __restrict__ out) {
    int i = blockIdx.x * blockDim.x + threadIdx.x;
    if (i < XCNT) {
        ((uint2*)g_xh)[i] = pack4h(((const float4*)x)[i]);
    } else if (i < XCNT + N4W) {
        int j = i - XCNT;
        ((uint2*)g_w1)[j] = pack4h(((const float4*)w1)[j]);
    } else {
        int j = i - XCNT - N4W;
        if (j < XCNT) ((float4*)out)[j] = make_float4(0.f, 0.f, 0.f, 0.f);
    }
}

// ---------------- mma.sync GEMM (R13 core; MODE1 epilogue fused-combine) --------
// MODE 0: H = gelu(X[rowtok]@W1^T + b1) -> fp16 (+ converts a W2 slice at top).
// MODE 1: out[tok] += (H@W2^T + b2)*gate  (fp32 atomics; commutative, exact).
template <int MODE, int KDIM>
__global__ void __launch_bounds__(256, 2) gemm_mma(
    const __half* __restrict__ Ah, const __half* __restrict__ Bh,
    const float* __restrict__ bias, int NDIM,
    const float* __restrict__ wsrc, __half* __restrict__ wdst, int wn4,
    float* __restrict__ outp) {

    int tid  = threadIdx.x;
    int lane = tid & 31, wid = tid >> 5;

    // fused W2 conversion slice (MODE 0 only; before any early return)
    if (MODE == 0) {
        int nblk   = gridDim.x * gridDim.y;
        int bid    = blockIdx.y * gridDim.x + blockIdx.x;
        int stride = nblk * 256;
        for (int i = bid * 256 + tid; i < wn4; i += stride)
            ((uint2*)wdst)[i] = pack4h(((const float4*)wsrc)[i]);
    }

    int e  = g_tile_e[blockIdx.y];
    int m0 = blockIdx.y * 128;
    if (m0 >= g_aoff[e] + g_counts[e]) return;
    int n0    = blockIdx.x * 128;
    int bbase = e * NDIM + n0;

    extern __shared__ char smem[];
    uint32_t sb = s2u(smem);
    int* rowtok_s = (int*)(smem + SMEM_PIPE);
    int wm = wid >> 2, wn = wid & 3;   // 2x4 warp grid, warp tile 64x32

    if (MODE == 0) {
        if (tid < 128) {
            int t = g_rowtok[m0 + tid];
            rowtok_s[tid] = (t < 0) ? 0 : t;   // padded rows -> token 0 (discarded)
        }
        __syncthreads();
    }

    const int NCH = KDIM / KCH;

    auto load_stage = [&](int c, int st) {
        int k0 = c * KCH;
        uint32_t stg = sb + st * STAGE_B;
#pragma unroll
        for (int i = 0; i < 8; i++) {               // 2 tiles * 1024 chunks / 256 thr
            int ci = i * 256 + tid;
            int tile = ci >> 10, rc = ci & 1023, row = rc >> 3, c16 = rc & 7;
            uint32_t dst = stg + tile * TILE_B + row * (LDSE * 2) + c16 * 16;
            const __half* src;
            if (tile == 0) {
                if (MODE == 0) src = Ah + (size_t)rowtok_s[row] * KDIM;
                else           src = Ah + (size_t)(m0 + row) * KDIM;
            } else {
                src = Bh + (size_t)(bbase + row) * KDIM;
            }
            cpasync16(dst, src + k0 + c16 * 8);
        }
        cp_commit();
    };

    int aoff = (wm * 64 + (lane & 15)) * LDSE + (lane >> 4) * 8;
    int boff = (wn * 32 + ((lane >> 4) << 3) + (lane & 7)) * LDSE + ((lane >> 3) & 1) * 8;

    float acc[4][4][4];
#pragma unroll
    for (int a = 0; a < 4; a++)
#pragma unroll
        for (int b = 0; b < 4; b++)
#pragma unroll
            for (int q = 0; q < 4; q++) acc[a][b][q] = 0.f;

    load_stage(0, 0);
    load_stage(1, 1);

    for (int c = 0; c < NCH; c++) {
        if (c + 1 < NCH) asm volatile("cp.async.wait_group 1;" ::: "memory");
        else             asm volatile("cp.async.wait_group 0;" ::: "memory");
        __syncthreads();
        if (c + 2 < NCH) load_stage(c + 2, (c + 2) % NSTAGE);

        uint32_t stg = sb + (c % NSTAGE) * STAGE_B;
        uint32_t aH = stg + aoff * 2;
        uint32_t bH = stg + TILE_B + boff * 2;

#pragma unroll
        for (int kk = 0; kk < 4; kk++) {
            uint32_t k2 = kk * 32;   // 16 fp16 = 32 bytes
            uint32_t ah[4][4], bh[2][4];
#pragma unroll
            for (int g = 0; g < 2; g++) ldmx4(bh[g], bH + g * (16 * LDSE * 2) + k2);
#pragma unroll
            for (int f = 0; f < 4; f++) ldmx4(ah[f], aH + f * (16 * LDSE * 2) + k2);
#pragma unroll
            for (int mi = 0; mi < 4; mi++)
#pragma unroll
                for (int g = 0; g < 2; g++) {
                    mma16816(acc[mi][g * 2 + 0], ah[mi], &bh[g][0]);
                    mma16816(acc[mi][g * 2 + 1], ah[mi], &bh[g][2]);
                }
        }
    }

    // ---------------- epilogue ----------------
    if (MODE == 0) {
        __syncthreads();   // pipeline smem no longer needed; reuse for staging
        uint32_t wsm = sb + wid * (64 * HSTG);
#pragma unroll
        for (int mi = 0; mi < 4; mi++)
#pragma unroll
            for (int rr = 0; rr < 2; rr++) {
                int rl = mi * 16 + rr * 8 + (lane >> 2);
#pragma unroll
                for (int ni = 0; ni < 4; ni++) {
                    int cl = ni * 8 + (lane & 3) * 2;
                    int gcol = n0 + wn * 32 + cl;
                    float v0 = acc[mi][ni][rr * 2 + 0] + bias[e * NDIM + gcol];
                    float v1 = acc[mi][ni][rr * 2 + 1] + bias[e * NDIM + gcol + 1];
                    v0 = 0.5f * v0 * (1.f + erff(v0 * 0.70710678118654752f));
                    v1 = 0.5f * v1 * (1.f + erff(v1 * 0.70710678118654752f));
                    __half h0 = __float2half_rn(v0), h1 = __float2half_rn(v1);
                    uint32_t hp = (uint32_t)__half_as_ushort(h0) | ((uint32_t)__half_as_ushort(h1) << 16);
                    asm volatile("st.shared.b32 [%0], %1;" :: "r"(wsm + rl * HSTG + cl * 2), "r"(hp));
                }
            }
        __syncwarp();
#pragma unroll
        for (int i = 0; i < 8; i++) {
            int rl = i * 8 + (lane >> 2), seg = lane & 3;
            uint4 v;
            asm volatile("ld.shared.v4.b32 {%0,%1,%2,%3}, [%4];"
                         : "=r"(v.x), "=r"(v.y), "=r"(v.z), "=r"(v.w)
                         : "r"(wsm + rl * HSTG + seg * 16));
            int r = m0 + wm * 64 + rl;
            *(uint4*)&g_h[(size_t)r * FF_DIM + n0 + wn * 32 + seg * 8] = v;
        }
    } else {
        // fused combine: out[tok] += (acc + bias) * gate   (fp32 add of exactly
        // two per-token contributions -> commutative -> bit-deterministic)
#pragma unroll
        for (int mi = 0; mi < 4; mi++)
#pragma unroll
            for (int rr = 0; rr < 2; rr++) {
                int r = m0 + wm * 64 + mi * 16 + rr * 8 + (lane >> 2);
                int tok = g_rowtok[r];
                if (tok < 0) continue;                 // padded row
                float gate = g_rowgate[r];
                float* orow = outp + (size_t)tok * C_DIM;
#pragma unroll
                for (int ni = 0; ni < 4; ni++) {
                    int cl = ni * 8 + (lane & 3) * 2;
                    int gcol = n0 + wn * 32 + cl;
                    float v0 = (acc[mi][ni][rr * 2 + 0] + bias[e * NDIM + gcol]) * gate;
                    float v1 = (acc[mi][ni][rr * 2 + 1] + bias[e * NDIM + gcol + 1]) * gate;
                    atomicAdd(orow + gcol,     v0);
                    atomicAdd(orow + gcol + 1, v1);
                }
            }
    }
}

// ---------------- host ----------------
extern "C" void kernel_launch(void* const* d_in, const int* in_sizes, int n_in,
                              void* d_out, int out_size) {
    const float* x  = (const float*)d_in[0];
    const float* rw = (const float*)d_in[1];
    const float* w1 = (const float*)d_in[2];
    const float* b1 = (const float*)d_in[3];
    const float* w2 = (const float*)d_in[4];
    const float* b2 = (const float*)d_in[5];
    float* out = (float*)d_out;

    void *pX, *pW1, *pW2, *pH;
    cudaGetSymbolAddress(&pX, g_xh);
    cudaGetSymbolAddress(&pW1, g_w1);
    cudaGetSymbolAddress(&pW2, g_w2);
    cudaGetSymbolAddress(&pH, g_h);

    cudaFuncSetAttribute(gemm_mma<0, C_DIM>,  cudaFuncAttributeMaxDynamicSharedMemorySize, SMEM_TOTAL);
    cudaFuncSetAttribute(gemm_mma<1, FF_DIM>, cudaFuncAttributeMaxDynamicSharedMemorySize, SMEM_TOTAL);

    init_kernel<<<PROWS / 256, 256>>>();
    router_kernel<<<(T_TOK * 32) / 256, 256>>>(x, rw);
    scan_kernel<<<1, 1>>>();
    scatter_kernel<<<T_TOK / 256, 256>>>();
    prep_kernel<<<(2 * XCNT + N4W) / 256, 256>>>(x, w1, out);

    dim3 g1(FF_DIM / 128, MTILES);   // (32, 72)
    gemm_mma<0, C_DIM><<<g1, 256, SMEM_TOTAL>>>(
        (const __half*)pX, (const __half*)pW1, b1, FF_DIM,
        w2, (__half*)pW2, N4W, nullptr);

    dim3 g2(C_DIM / 128, MTILES);    // (8, 72)
    gemm_mma<1, FF_DIM><<<g2, 256, SMEM_TOTAL>>>(
        (const __half*)pH, (const __half*)pW2, b2, C_DIM,
        nullptr, nullptr, 0, out);
}